// round 6
// baseline (speedup 1.0000x reference)
#include <cuda_runtime.h>
#include <math.h>

#define BATCH 2
#define CIN   256
#define CHID  128
#define TT    128     // tscale
#define NSMP  32      // num_sample
#define CROI  512
#define COUT  128
#define DSC   128     // dscale
#define BO    (BATCH*CROI)   // 1024
#define NDM   (DSC*TT)       // 16384

// Scratch
__device__ float g_h[BATCH*CHID*TT];            // h[b][c][t]
__device__ float g_w3dT[NSMP*CROI*CHID];        // w3dT[n][o][c]
__device__ float g_P[(size_t)NSMP*TT*BO];       // P[n][t][bo], bo = b*512+o
__device__ float g_M3[(size_t)BO*NDM];          // m3[bo][d*128+m]

__device__ __forceinline__ unsigned smem_u32(const void* p) {
    return (unsigned)__cvta_generic_to_shared(p);
}
__device__ __forceinline__ void cp_async16(unsigned dst, const void* src, int sz) {
    asm volatile("cp.async.cg.shared.global [%0], [%1], 16, %2;\n"
                 :: "r"(dst), "l"(src), "r"(sz));
}
__device__ __forceinline__ void cp_commit() {
    asm volatile("cp.async.commit_group;\n");
}

// ---- packed fp32 pair helpers (f32x2; numerics identical to scalar FFMA)
typedef unsigned long long ull;
__device__ __forceinline__ ull pack2(float a, float b) {
    ull r; asm("mov.b64 %0, {%1, %2};" : "=l"(r) : "f"(a), "f"(b)); return r;
}
__device__ __forceinline__ float2 unpack2(ull v) {
    float2 r; asm("mov.b64 {%0, %1}, %2;" : "=f"(r.x), "=f"(r.y) : "l"(v)); return r;
}
__device__ __forceinline__ void fma2(ull& d, ull a, ull b) {
    asm("fma.rn.f32x2 %0, %1, %2, %0;" : "+l"(d) : "l"(a), "l"(b));
}

// ---------------------------------------------------------------------------
// K1: conv1d(256->128, k=3, pad=1) + bias + ReLU
// ---------------------------------------------------------------------------
__global__ __launch_bounds__(128) void conv1d_kernel(
    const float* __restrict__ x, const float* __restrict__ w,
    const float* __restrict__ bias)
{
    int bo = blockIdx.x;
    int b = bo >> 7, o = bo & 127;
    int t = threadIdx.x;
    __shared__ float ws[CIN*3];
    for (int idx = t; idx < CIN*3; idx += 128) ws[idx] = w[o*CIN*3 + idx];
    __syncthreads();
    const float* xb = x + (size_t)b*CIN*TT;
    float acc = bias[o];
    #pragma unroll 4
    for (int i = 0; i < CIN; ++i) {
        float xm = (t > 0)    ? xb[i*TT + t - 1] : 0.f;
        float xc =              xb[i*TT + t];
        float xp = (t < TT-1) ? xb[i*TT + t + 1] : 0.f;
        acc = fmaf(xm, ws[i*3+0], acc);
        acc = fmaf(xc, ws[i*3+1], acc);
        acc = fmaf(xp, ws[i*3+2], acc);
    }
    g_h[(b*CHID + o)*TT + t] = fmaxf(acc, 0.f);
}

// ---------------------------------------------------------------------------
// K2a: transpose w3d[o][c][n] -> g_w3dT[n][o][c]
// ---------------------------------------------------------------------------
__global__ __launch_bounds__(256) void w3d_transpose_kernel(
    const float* __restrict__ w3d)
{
    int o  = blockIdx.x;
    int c0 = blockIdx.y * 32;
    __shared__ float tile[32][33];
    int tn = threadIdx.x & 31;
    int tg = threadIdx.x >> 5;
    for (int cc = tg; cc < 32; cc += 8)
        tile[cc][tn] = w3d[((size_t)(o*CHID + c0 + cc))*NSMP + tn];
    __syncthreads();
    int tc = threadIdx.x & 31;
    for (int nn = tg; nn < 32; nn += 8)
        g_w3dT[((size_t)(nn*CROI + o))*CHID + c0 + tc] = tile[tc][nn];
}

// ---------------------------------------------------------------------------
// K2b: P[n][t][b*512+o] = sum_c w3dT[n][o][c] * h[b][c][t]
// ---------------------------------------------------------------------------
__global__ __launch_bounds__(256) void pmat_kernel()
{
    int o0 = blockIdx.x * 128;
    int n  = blockIdx.y;
    int b  = blockIdx.z;
    __shared__ float As[16][132];
    __shared__ float Bs[16][128];
    const float* A  = g_w3dT + (size_t)(n*CROI + o0)*CHID;
    const float* Bm = g_h + (size_t)b*CHID*TT;
    int tid = threadIdx.x;
    int ty = tid >> 4, tx = tid & 15;
    float acc[8][8];
    #pragma unroll
    for (int i = 0; i < 8; ++i)
        #pragma unroll
        for (int j = 0; j < 8; ++j) acc[i][j] = 0.f;

    for (int c0 = 0; c0 < CHID; c0 += 16) {
        {
            int r  = tid >> 2;
            int c4 = (tid & 3) * 4;
            #pragma unroll
            for (int p = 0; p < 2; ++p) {
                float4 v = *(const float4*)&A[(r + 64*p)*CHID + c0 + c4];
                As[c4+0][r+64*p] = v.x;
                As[c4+1][r+64*p] = v.y;
                As[c4+2][r+64*p] = v.z;
                As[c4+3][r+64*p] = v.w;
            }
        }
        {
            int r  = tid >> 5;
            int c4 = (tid & 31) * 4;
            #pragma unroll
            for (int p = 0; p < 2; ++p) {
                float4 v = *(const float4*)&Bm[(c0 + r + 8*p)*TT + c4];
                *(float4*)&Bs[r + 8*p][c4] = v;
            }
        }
        __syncthreads();
        #pragma unroll
        for (int kk = 0; kk < 16; ++kk) {
            float4 a0 = *(const float4*)&As[kk][ty*8];
            float4 a1 = *(const float4*)&As[kk][ty*8+4];
            float4 b0 = *(const float4*)&Bs[kk][tx*8];
            float4 b1 = *(const float4*)&Bs[kk][tx*8+4];
            float av[8] = {a0.x,a0.y,a0.z,a0.w,a1.x,a1.y,a1.z,a1.w};
            float bv[8] = {b0.x,b0.y,b0.z,b0.w,b1.x,b1.y,b1.z,b1.w};
            #pragma unroll
            for (int i = 0; i < 8; ++i)
                #pragma unroll
                for (int j = 0; j < 8; ++j)
                    acc[i][j] = fmaf(av[i], bv[j], acc[i][j]);
        }
        __syncthreads();
    }
    #pragma unroll
    for (int j = 0; j < 8; ++j) {
        int t = tx*8 + j;
        size_t base = ((size_t)(n*TT + t))*BO + b*CROI + o0;
        #pragma unroll
        for (int i = 0; i < 8; ++i)
            g_P[base + ty*8 + i] = acc[i][j];
    }
}

// ---------------------------------------------------------------------------
// K3: conv-form interp, 256 threads / 8 warps, m-tile 64.
// Per n: 3 taps collapse to 8-wide conv wv[n][0..7] (1/3 folded).
// out[m] = sum_r wv[r]*P[n][t0b+m+r][bo]; rows outside [0,128) zero.
// Trunc-semantics boundary (s in [-1,0)) via exact fp64 per-column
// correction cw * P[n][0][bo] at column mj.
// Warp cg owns m-cols cg*8..cg*8+7; lane owns 4 bo.
// Window: 71 rows x 128 bo, cp.async double-buffered (dynamic smem).
// Grid: x = m-tile of 64 (2), y = d (128), z = bo-tile of 128 (8).
// ---------------------------------------------------------------------------
#define WROWS 71
#define WB    128
#define SPAD  129
#define INTERP_DSM ((2*WROWS*WB + 2*128) * 4)
__global__ __launch_bounds__(256) void interp_kernel(const float* __restrict__ b3d)
{
    int m0  = blockIdx.x * 64;
    int d   = blockIdx.y;
    int bo0 = blockIdx.z * 128;
    int tid = threadIdx.x;

    // -------- fully invalid tile: relu(bias) fill --------
    if (m0 >= TT - d) {
        int f4 = tid & 15;                 // 16 float4 per row of 64 cols
        int r0 = tid >> 4;                 // 16 rows per pass
        #pragma unroll
        for (int k = 0; k < 8; ++k) {
            int r = r0 + 16*k;
            float v = fmaxf(b3d[(bo0 + r) & 511], 0.f);
            float4 vv = make_float4(v, v, v, v);
            *(float4*)&g_M3[(size_t)(bo0 + r)*NDM + d*TT + m0 + f4*4] = vv;
        }
        return;
    }

    extern __shared__ __align__(16) float dsm[];
    float* winb[2] = { dsm, dsm + WROWS*WB };
    float* r0b     = dsm + 2*WROWS*WB;          // [2][128]
    __shared__ float s_wv[NSMP][8];
    __shared__ int   s_t0b[NSMP];
    __shared__ int   s_mj[96];
    __shared__ float s_cw[96];

    // -------- build conv weights + boundary-correction tables (fp64) -----
    ((float*)s_wv)[tid] = 0.f;                  // 256 entries = whole table
    __syncthreads();
    if (tid < NSMP) {
        int n = tid;
        double h = 0.5 * (double)(d + 1);
        double p = (2.0*(double)d + 1.0) / 95.0;
        int t0b = 0;
        #pragma unroll
        for (int j = 0; j < 3; ++j) {
            int i = 3*n + j;
            double q = p * (double)i;
            double s = ((double)m0 - h) + q;    // numpy op order
            double fs = floor(s);
            int t0 = (int)fs;
            float f = (float)(s - fs);
            if (j == 0) { t0b = t0; s_t0b[n] = t0; }
            int dlt = t0 - t0b;                 // 0..6
            s_wv[n][dlt]   += (1.0f - f) * (1.0f/3.0f);
            s_wv[n][dlt+1] += f * (1.0f/3.0f);
            int mj = -1 - t0;                   // column with s in [-1,0)
            float cw = 0.f;
            if (mj >= 0 && mj < 64) {
                double ss = ((double)(m0 + mj) - h) + q;  // that column's fp64
                cw = (((ss > -1.0) ? 1.0f : 0.0f) - f) * (1.0f/3.0f);
            } else mj = -1;
            s_mj[i] = mj;
            s_cw[i] = cw;
        }
    }
    __syncthreads();

    int bl = tid & 31;     // lane: 4 bo at 4*bl
    int cg = tid >> 5;     // warp: m-cols cg*8..cg*8+7
    ull accp[8][2];
    #pragma unroll
    for (int c = 0; c < 8; ++c) { accp[c][0] = 0ull; accp[c][1] = 0ull; }

    // -------- window fill via cp.async: rows t<0, t>127 are ZERO ----------
    int fr = tid >> 5;            // 0..7
    int fc = (tid & 31) * 4;      // float col
    #define FILL(BUF, N) do {                                                  \
        int wlo_ = s_t0b[N];                                                   \
        const float* srcb = g_P + ((size_t)(N)*TT)*BO + bo0 + fc;              \
        _Pragma("unroll")                                                      \
        for (int p_ = 0; p_ < 9; ++p_) {                                       \
            int r_ = fr + 8*p_;                                                \
            if (r_ < WROWS) {                                                  \
                int t_ = wlo_ + r_;                                            \
                int tc_ = min(max(t_, 0), TT-1);                               \
                int sz_ = (t_ >= 0 && t_ <= TT-1) ? 16 : 0;                    \
                cp_async16(smem_u32(&winb[BUF][r_*WB + fc]),                   \
                           srcb + (size_t)tc_*BO, sz_);                        \
            }                                                                  \
        }                                                                      \
        if (fr == 0)                                                           \
            cp_async16(smem_u32(&r0b[(BUF)*128 + fc]), srcb, 16);              \
    } while (0)

    FILL(0, 0);
    cp_commit();

    for (int n = 0; n < NSMP; ++n) {
        int buf = n & 1;
        if (n < NSMP-1) { FILL(buf^1, n+1); cp_commit(); }
        if (n < NSMP-1) { asm volatile("cp.async.wait_group 1;\n" ::: "memory"); }
        else            { asm volatile("cp.async.wait_group 0;\n" ::: "memory"); }
        __syncthreads();

        const float* wb = winb[buf];
        ull wp[8];
        #pragma unroll
        for (int r = 0; r < 8; ++r) { float c = s_wv[n][r]; wp[r] = pack2(c, c); }

        // stream 15 window rows; row k feeds acc cols [k-7, k] ∩ [0,7]
        #pragma unroll
        for (int k = 0; k < 15; ++k) {
            ulonglong2 v = *(const ulonglong2*)&wb[(cg*8 + k)*WB + 4*bl];
            #pragma unroll
            for (int cc = 0; cc < 8; ++cc) {
                if (cc >= ((k > 7) ? (k - 7) : 0) && cc <= ((k < 8) ? k : 7)) {
                    fma2(accp[cc][0], wp[k-cc], v.x);
                    fma2(accp[cc][1], wp[k-cc], v.y);
                }
            }
        }

        // boundary corrections (warp-uniform)
        ulonglong2 r0v = *(const ulonglong2*)&r0b[buf*128 + 4*bl];
        #pragma unroll
        for (int j = 0; j < 3; ++j) {
            int cc = s_mj[3*n + j] - cg*8;
            if ((unsigned)cc < 8u) {
                float cw = s_cw[3*n + j];
                ull cwp = pack2(cw, cw);
                fma2(accp[cc][0], cwp, r0v.x);
                fma2(accp[cc][1], cwp, r0v.y);
            }
        }
        __syncthreads();
    }

    // -------- transpose via smem (stride 129), bias + relu, store ---------
    float* stage = winb[0];                // 64*129 = 8256 <= 71*128 = 9088
    #pragma unroll
    for (int cc = 0; cc < 8; ++cc) {
        float2 lo = unpack2(accp[cc][0]);
        float2 hi = unpack2(accp[cc][1]);
        float* s = &stage[(cg*8 + cc)*SPAD + 4*bl];
        s[0] = lo.x; s[1] = lo.y; s[2] = hi.x; s[3] = hi.y;
    }
    __syncthreads();

    int vlim = TT - 1 - d - m0;            // col m valid iff m <= vlim
    #pragma unroll
    for (int rr = 0; rr < 16; ++rr) {
        int r = cg*16 + rr;                // bo row 0..127
        float bias = b3d[(bo0 + r) & 511];
        size_t base = (size_t)(bo0 + r)*NDM + d*TT + m0;
        #pragma unroll
        for (int hh = 0; hh < 2; ++hh) {
            int m = bl + 32*hh;
            float v = stage[m*SPAD + r] + bias;
            v = (m <= vlim) ? fmaxf(v, 0.f) : fmaxf(bias, 0.f);
            g_M3[base + m] = v;
        }
    }
}

// ---------------------------------------------------------------------------
// K4: out[b][o2][dm] = relu( b2d[o2] + sum_o w2d[o2][o] * M3[b*512+o][dm] )
// 128x128 tile, 8x8 micro with packed f32x2 FMAs.
// ---------------------------------------------------------------------------
__global__ __launch_bounds__(256) void out_gemm_kernel(
    const float* __restrict__ w2d, const float* __restrict__ b2d,
    float* __restrict__ out)
{
    int dm0 = blockIdx.x * 128;
    int b   = blockIdx.y;
    __shared__ __align__(16) float As[16][132];
    __shared__ __align__(16) float Bs[16][132];
    int tid = threadIdx.x;
    int ty = tid >> 4, tx = tid & 15;
    ull accp[8][4];
    #pragma unroll
    for (int i = 0; i < 8; ++i)
        #pragma unroll
        for (int j = 0; j < 4; ++j) accp[i][j] = 0ull;

    for (int k0 = 0; k0 < CROI; k0 += 16) {
        {   // A: w2d[o2][k] -> As[k][o2]
            int r  = tid >> 2;
            int c4 = (tid & 3) * 4;
            #pragma unroll
            for (int p = 0; p < 2; ++p) {
                float4 v = *(const float4*)&w2d[(size_t)(r + 64*p)*CROI + k0 + c4];
                As[c4+0][r+64*p] = v.x;
                As[c4+1][r+64*p] = v.y;
                As[c4+2][r+64*p] = v.z;
                As[c4+3][r+64*p] = v.w;
            }
        }
        {   // B: M3 rows b*512+k0..+15, cols dm0..+127
            int kk = tid >> 4;
            int j4 = (tid & 15) * 4;
            #pragma unroll
            for (int p = 0; p < 2; ++p) {
                float4 v = *(const float4*)&g_M3[(size_t)(b*CROI + k0 + kk)*NDM + dm0 + j4 + 64*p];
                *(float4*)&Bs[kk][j4 + 64*p] = v;
            }
        }
        __syncthreads();
        #pragma unroll
        for (int kk = 0; kk < 16; ++kk) {
            float4 a0 = *(const float4*)&As[kk][ty*8];
            float4 a1 = *(const float4*)&As[kk][ty*8+4];
            ulonglong2 bA = *(const ulonglong2*)&Bs[kk][tx*8];
            ulonglong2 bB = *(const ulonglong2*)&Bs[kk][tx*8+4];
            ull bp[4] = {bA.x, bA.y, bB.x, bB.y};
            float av[8] = {a0.x,a0.y,a0.z,a0.w,a1.x,a1.y,a1.z,a1.w};
            #pragma unroll
            for (int i = 0; i < 8; ++i) {
                ull ap = pack2(av[i], av[i]);
                #pragma unroll
                for (int j = 0; j < 4; ++j)
                    fma2(accp[i][j], ap, bp[j]);
            }
        }
        __syncthreads();
    }
    #pragma unroll
    for (int i = 0; i < 8; ++i) {
        int o2 = ty*8 + i;
        float bias = b2d[o2];
        size_t base = (size_t)(b*COUT + o2)*NDM + dm0 + tx*8;
        #pragma unroll
        for (int j = 0; j < 4; ++j) {
            float2 v = unpack2(accp[i][j]);
            out[base + 2*j + 0] = fmaxf(v.x + bias, 0.f);
            out[base + 2*j + 1] = fmaxf(v.y + bias, 0.f);
        }
    }
}

// ---------------------------------------------------------------------------
// Inputs: 0:x 1:w_red 2:b_red 3:w3d 4:b3d 5:w2d 6:b2d 7:sample_mask (unused)
// ---------------------------------------------------------------------------
extern "C" void kernel_launch(void* const* d_in, const int* in_sizes, int n_in,
                              void* d_out, int out_size)
{
    const float* x     = (const float*)d_in[0];
    const float* w_red = (const float*)d_in[1];
    const float* b_red = (const float*)d_in[2];
    const float* w3d   = (const float*)d_in[3];
    const float* b3d   = (const float*)d_in[4];
    const float* w2d   = (const float*)d_in[5];
    const float* b2d   = (const float*)d_in[6];
    float* out = (float*)d_out;

    cudaFuncSetAttribute(interp_kernel,
                         cudaFuncAttributeMaxDynamicSharedMemorySize, INTERP_DSM);

    conv1d_kernel<<<BATCH*CHID, 128>>>(x, w_red, b_red);
    w3d_transpose_kernel<<<dim3(CROI, 4), 256>>>(w3d);
    pmat_kernel<<<dim3(4, NSMP, BATCH), 256>>>();
    interp_kernel<<<dim3(2, DSC, BO/128), 256, INTERP_DSM>>>(b3d);
    out_gemm_kernel<<<dim3(NDM/128, BATCH), 256>>>(w2d, b2d, out);
}

// round 13
// speedup vs baseline: 1.3220x; 1.3220x over previous
#include <cuda_runtime.h>
#include <math.h>

#define BATCH 2
#define CIN   256
#define CHID  128
#define TT    128     // tscale
#define NSMP  32      // num_sample
#define CROI  512
#define COUT  128
#define DSC   128     // dscale
#define BO    (BATCH*CROI)   // 1024
#define NDM   (DSC*TT)       // 16384

// Scratch
__device__ float g_h[BATCH*CHID*TT];            // h[b][c][t]
__device__ float g_w3dT[NSMP*CROI*CHID];        // w3dT[n][o][c]
__device__ float g_P[(size_t)NSMP*TT*BO];       // P[n][t][bo], bo = b*512+o
__device__ float g_M3[(size_t)BO*NDM];          // m3[bo][d*128+m]

__device__ __forceinline__ unsigned smem_u32(const void* p) {
    return (unsigned)__cvta_generic_to_shared(p);
}
__device__ __forceinline__ void cp_async16(unsigned dst, const void* src, int sz) {
    asm volatile("cp.async.cg.shared.global [%0], [%1], 16, %2;\n"
                 :: "r"(dst), "l"(src), "r"(sz));
}
__device__ __forceinline__ void cp_commit() {
    asm volatile("cp.async.commit_group;\n");
}

// ---------------------------------------------------------------------------
// K1: conv1d(256->128, k=3, pad=1) + bias + ReLU
// ---------------------------------------------------------------------------
__global__ __launch_bounds__(128) void conv1d_kernel(
    const float* __restrict__ x, const float* __restrict__ w,
    const float* __restrict__ bias)
{
    int bo = blockIdx.x;
    int b = bo >> 7, o = bo & 127;
    int t = threadIdx.x;
    __shared__ float ws[CIN*3];
    for (int idx = t; idx < CIN*3; idx += 128) ws[idx] = w[o*CIN*3 + idx];
    __syncthreads();
    const float* xb = x + (size_t)b*CIN*TT;
    float acc = bias[o];
    #pragma unroll 4
    for (int i = 0; i < CIN; ++i) {
        float xm = (t > 0)    ? xb[i*TT + t - 1] : 0.f;
        float xc =              xb[i*TT + t];
        float xp = (t < TT-1) ? xb[i*TT + t + 1] : 0.f;
        acc = fmaf(xm, ws[i*3+0], acc);
        acc = fmaf(xc, ws[i*3+1], acc);
        acc = fmaf(xp, ws[i*3+2], acc);
    }
    g_h[(b*CHID + o)*TT + t] = fmaxf(acc, 0.f);
}

// ---------------------------------------------------------------------------
// K2a: transpose w3d[o][c][n] -> g_w3dT[n][o][c]
// ---------------------------------------------------------------------------
__global__ __launch_bounds__(256) void w3d_transpose_kernel(
    const float* __restrict__ w3d)
{
    int o  = blockIdx.x;
    int c0 = blockIdx.y * 32;
    __shared__ float tile[32][33];
    int tn = threadIdx.x & 31;
    int tg = threadIdx.x >> 5;
    for (int cc = tg; cc < 32; cc += 8)
        tile[cc][tn] = w3d[((size_t)(o*CHID + c0 + cc))*NSMP + tn];
    __syncthreads();
    int tc = threadIdx.x & 31;
    for (int nn = tg; nn < 32; nn += 8)
        g_w3dT[((size_t)(nn*CROI + o))*CHID + c0 + tc] = tile[tc][nn];
}

// ---------------------------------------------------------------------------
// K2b: P[n][t][b*512+o] = sum_c w3dT[n][o][c] * h[b][c][t]
// ---------------------------------------------------------------------------
__global__ __launch_bounds__(256) void pmat_kernel()
{
    int o0 = blockIdx.x * 128;
    int n  = blockIdx.y;
    int b  = blockIdx.z;
    __shared__ float As[16][132];
    __shared__ float Bs[16][128];
    const float* A  = g_w3dT + (size_t)(n*CROI + o0)*CHID;
    const float* Bm = g_h + (size_t)b*CHID*TT;
    int tid = threadIdx.x;
    int ty = tid >> 4, tx = tid & 15;
    float acc[8][8];
    #pragma unroll
    for (int i = 0; i < 8; ++i)
        #pragma unroll
        for (int j = 0; j < 8; ++j) acc[i][j] = 0.f;

    for (int c0 = 0; c0 < CHID; c0 += 16) {
        {
            int r  = tid >> 2;
            int c4 = (tid & 3) * 4;
            #pragma unroll
            for (int p = 0; p < 2; ++p) {
                float4 v = *(const float4*)&A[(r + 64*p)*CHID + c0 + c4];
                As[c4+0][r+64*p] = v.x;
                As[c4+1][r+64*p] = v.y;
                As[c4+2][r+64*p] = v.z;
                As[c4+3][r+64*p] = v.w;
            }
        }
        {
            int r  = tid >> 5;
            int c4 = (tid & 31) * 4;
            #pragma unroll
            for (int p = 0; p < 2; ++p) {
                float4 v = *(const float4*)&Bm[(c0 + r + 8*p)*TT + c4];
                *(float4*)&Bs[r + 8*p][c4] = v;
            }
        }
        __syncthreads();
        #pragma unroll
        for (int kk = 0; kk < 16; ++kk) {
            float4 a0 = *(const float4*)&As[kk][ty*8];
            float4 a1 = *(const float4*)&As[kk][ty*8+4];
            float4 b0 = *(const float4*)&Bs[kk][tx*8];
            float4 b1 = *(const float4*)&Bs[kk][tx*8+4];
            float av[8] = {a0.x,a0.y,a0.z,a0.w,a1.x,a1.y,a1.z,a1.w};
            float bv[8] = {b0.x,b0.y,b0.z,b0.w,b1.x,b1.y,b1.z,b1.w};
            #pragma unroll
            for (int i = 0; i < 8; ++i)
                #pragma unroll
                for (int j = 0; j < 8; ++j)
                    acc[i][j] = fmaf(av[i], bv[j], acc[i][j]);
        }
        __syncthreads();
    }
    #pragma unroll
    for (int j = 0; j < 8; ++j) {
        int t = tx*8 + j;
        size_t base = ((size_t)(n*TT + t))*BO + b*CROI + o0;
        #pragma unroll
        for (int i = 0; i < 8; ++i)
            g_P[base + ty*8 + i] = acc[i][j];
    }
}

// ---------------------------------------------------------------------------
// K3: analytic interp, m-tile 64 (direct taps; round-3 math, wider tile).
// m3[bo][d*128+m] = relu( b3d + (1/3)*sum_{i=0..95} tap_i )
// tap_i at column m: s = (m - (d+1)/2) + i*(2d+1)/95 (fp64, numpy op order)
//   s >= 0            : (1-f)*P[t0] + f*P[t0+1]   (rows > 127 are zero)
//   -1 < s < 0        : exactly 1.0 * P[0]
//   s <= -1 (incl ==) : 0
// Window rows t<0 zero-filled; [-1,0) via base tap + one-column correction
// cw*row0 with cw = (s* > -1 ? 1 : 0) - f recomputed per-column in fp64.
// Block: 256 threads = 8 warps (warp mg: m-cols mg*8..+7) x 32 lanes (4 bo).
// Window: 71 rows x 128 bo, double-buffered in DYNAMIC smem.
// Grid: x = m-tile of 64 (2), y = d (128), z = bo-tile of 128 (8).
// ---------------------------------------------------------------------------
#define WROWS 71
#define WB    128
#define SPAD  129
#define INTERP_DSM ((2*WROWS*WB + 2*128) * 4)
__global__ __launch_bounds__(256) void interp_kernel(const float* __restrict__ b3d)
{
    int m0  = blockIdx.x * 64;
    int d   = blockIdx.y;
    int bo0 = blockIdx.z * 128;
    int tid = threadIdx.x;

    // -------- fully invalid tile: relu(bias) fill --------
    if (m0 >= TT - d) {
        int f4 = tid & 15;                 // 16 float4 per row of 64 cols
        int r0 = tid >> 4;                 // 16 rows per pass
        #pragma unroll
        for (int k = 0; k < 8; ++k) {
            int r = r0 + 16*k;
            float v = fmaxf(b3d[(bo0 + r) & 511], 0.f);
            float4 vv = make_float4(v, v, v, v);
            *(float4*)&g_M3[(size_t)(bo0 + r)*NDM + d*TT + m0 + f4*4] = vv;
        }
        return;
    }

    extern __shared__ float dsm[];
    float* winb0 = dsm;
    float* winb1 = dsm + WROWS*WB;
    float* r0b   = dsm + 2*WROWS*WB;       // [2][128]
    __shared__ int   s_t0[96];
    __shared__ float s_f[96];
    __shared__ int   s_jf[96];
    __shared__ float s_cw[96];

    // -------- fp64 sample table (bit-matches numpy at the -1 boundary) ----
    if (tid < 96) {
        int i = tid;
        double h = 0.5 * (double)(d + 1);
        double p = (2.0*(double)d + 1.0) / 95.0;
        double q = p * (double)i;
        double s = ((double)m0 - h) + q;
        double fs = floor(s);
        int t0 = (int)fs;
        float f = (float)(s - fs);
        s_t0[i] = t0;
        s_f[i]  = f;
        int jf = -1 - t0;                  // column with s in [-1, 0)
        float cw = 0.f;
        if (jf >= 0 && jf < 64) {
            double sstar = ((double)(m0 + jf) - h) + q;  // that column's own fp64
            cw = ((sstar > -1.0) ? 1.0f : 0.0f) - f;
        } else jf = -1;
        s_jf[i] = jf;
        s_cw[i] = cw;
    }
    __syncthreads();

    int bl = tid & 31;     // lane: 4 bo at 4*bl
    int mg = tid >> 5;     // warp: m-cols mg*8..mg*8+7
    float4 acc[8];
    #pragma unroll
    for (int c = 0; c < 8; ++c) acc[c] = make_float4(0.f, 0.f, 0.f, 0.f);

    // -------- window fill via cp.async: rows t<0 and t>127 are ZERO -------
    int fr = tid >> 5;            // 0..7
    int fc = (tid & 31) * 4;      // float col
    #define FILL(WPTR, BN, N) do {                                             \
        int wlo_ = s_t0[3*(N)];                                                \
        const float* srcb = g_P + ((size_t)(N)*TT)*BO + bo0 + fc;              \
        _Pragma("unroll")                                                      \
        for (int p_ = 0; p_ < 9; ++p_) {                                       \
            int r_ = fr + 8*p_;                                                \
            if (r_ < WROWS) {                                                  \
                int t_ = wlo_ + r_;                                            \
                int tc_ = min(max(t_, 0), TT-1);                               \
                int sz_ = (t_ >= 0 && t_ <= TT-1) ? 16 : 0;                    \
                cp_async16(smem_u32(&(WPTR)[r_*WB + fc]),                      \
                           srcb + (size_t)tc_*BO, sz_);                        \
            }                                                                  \
        }                                                                      \
        if (fr == 0)                                                           \
            cp_async16(smem_u32(&r0b[(BN)*128 + fc]), srcb, 16);               \
    } while (0)

    FILL(winb0, 0, 0);
    cp_commit();

    for (int n = 0; n < NSMP; ++n) {
        int buf = n & 1;
        if (n < NSMP-1) {
            if (buf) FILL(winb0, 0, n+1); else FILL(winb1, 1, n+1);
            cp_commit();
        }
        if (n < NSMP-1) { asm volatile("cp.async.wait_group 1;\n" ::: "memory"); }
        else            { asm volatile("cp.async.wait_group 0;\n" ::: "memory"); }
        __syncthreads();

        int wlo = s_t0[3*n];
        const float* wb = buf ? winb1 : winb0;
        float4 r0v = *(const float4*)&r0b[buf*128 + 4*bl];
        #pragma unroll
        for (int j = 0; j < 3; ++j) {
            int i = 3*n + j;
            int tt = s_t0[i] - wlo;
            float f = s_f[i];
            float w1 = 1.0f - f;
            int rb = tt + 8*mg;
            // 9 rows feed 8 columns: acc[cc] += w1*a[cc] + f*a[cc+1]
            float4 a[9];
            #pragma unroll
            for (int k = 0; k < 9; ++k)
                a[k] = *(const float4*)&wb[(rb + k)*WB + 4*bl];
            #pragma unroll
            for (int cc = 0; cc < 8; ++cc) {
                acc[cc].x += w1*a[cc].x + f*a[cc+1].x;
                acc[cc].y += w1*a[cc].y + f*a[cc+1].y;
                acc[cc].z += w1*a[cc].z + f*a[cc+1].z;
                acc[cc].w += w1*a[cc].w + f*a[cc+1].w;
            }
            // boundary correction: one column (one warp) gets cw * row0
            int jc = s_jf[i] - 8*mg;       // warp-uniform branch
            if ((unsigned)jc < 8u) {
                float cw = s_cw[i];
                #pragma unroll
                for (int cc = 0; cc < 8; ++cc) {
                    if (cc == jc) {
                        acc[cc].x += cw*r0v.x; acc[cc].y += cw*r0v.y;
                        acc[cc].z += cw*r0v.z; acc[cc].w += cw*r0v.w;
                    }
                }
            }
        }
        __syncthreads();
    }
    #undef FILL

    // -------- transpose via smem (stride 129), bias + relu, store ---------
    float* stage = winb0;                  // 64*129 = 8256 <= 71*128 = 9088
    const float third = 1.0f/3.0f;
    #pragma unroll
    for (int cc = 0; cc < 8; ++cc) {
        float* s = &stage[(mg*8 + cc)*SPAD + 4*bl];
        s[0] = acc[cc].x * third;
        s[1] = acc[cc].y * third;
        s[2] = acc[cc].z * third;
        s[3] = acc[cc].w * third;
    }
    __syncthreads();

    int vlim = TT - 1 - d - m0;            // col m valid iff m <= vlim
    #pragma unroll
    for (int rr = 0; rr < 16; ++rr) {
        int r = mg*16 + rr;                // bo row 0..127
        float bias = b3d[(bo0 + r) & 511];
        size_t base = (size_t)(bo0 + r)*NDM + d*TT + m0;
        #pragma unroll
        for (int hh = 0; hh < 2; ++hh) {
            int m = bl + 32*hh;
            float v = stage[m*SPAD + r] + bias;
            v = (m <= vlim) ? fmaxf(v, 0.f) : fmaxf(bias, 0.f);
            g_M3[base + m] = v;
        }
    }
}

// ---------------------------------------------------------------------------
// K4: out[b][o2][dm] = relu( b2d[o2] + sum_o w2d[o2][o] * M3[b*512+o][dm] )
// EXACT round-3 version (no skip — skip variants fault on this toolchain).
// ---------------------------------------------------------------------------
__global__ __launch_bounds__(256) void out_gemm_kernel(
    const float* __restrict__ w2d, const float* __restrict__ b2d,
    float* __restrict__ out)
{
    int dm0 = blockIdx.x * 64;
    int b   = blockIdx.y;
    __shared__ float As[16][132];
    __shared__ float Bs[16][68];
    int tid = threadIdx.x;
    int ty = tid >> 4, tx = tid & 15;
    float acc[8][4];
    #pragma unroll
    for (int i = 0; i < 8; ++i)
        #pragma unroll
        for (int j = 0; j < 4; ++j) acc[i][j] = 0.f;

    for (int k0 = 0; k0 < CROI; k0 += 16) {
        {
            int r  = tid >> 2;
            int c4 = (tid & 3) * 4;
            #pragma unroll
            for (int p = 0; p < 2; ++p) {
                float4 v = *(const float4*)&w2d[(size_t)(r + 64*p)*CROI + k0 + c4];
                As[c4+0][r+64*p] = v.x;
                As[c4+1][r+64*p] = v.y;
                As[c4+2][r+64*p] = v.z;
                As[c4+3][r+64*p] = v.w;
            }
        }
        {
            int kk = tid >> 4;
            int j4 = (tid & 15) * 4;
            float4 v = *(const float4*)&g_M3[(size_t)(b*CROI + k0 + kk)*NDM + dm0 + j4];
            *(float4*)&Bs[kk][j4] = v;
        }
        __syncthreads();
        #pragma unroll
        for (int kk = 0; kk < 16; ++kk) {
            float4 a0 = *(const float4*)&As[kk][ty*8];
            float4 a1 = *(const float4*)&As[kk][ty*8+4];
            float4 b0 = *(const float4*)&Bs[kk][tx*4];
            float av[8] = {a0.x,a0.y,a0.z,a0.w,a1.x,a1.y,a1.z,a1.w};
            float bv[4] = {b0.x,b0.y,b0.z,b0.w};
            #pragma unroll
            for (int i = 0; i < 8; ++i)
                #pragma unroll
                for (int j = 0; j < 4; ++j)
                    acc[i][j] = fmaf(av[i], bv[j], acc[i][j]);
        }
        __syncthreads();
    }
    #pragma unroll
    for (int i = 0; i < 8; ++i) {
        int o2 = ty*8 + i;
        float bias = b2d[o2];
        size_t base = (size_t)(b*COUT + o2)*NDM + dm0 + tx*4;
        #pragma unroll
        for (int j = 0; j < 4; ++j)
            out[base + j] = fmaxf(acc[i][j] + bias, 0.f);
    }
}

// ---------------------------------------------------------------------------
// Inputs: 0:x 1:w_red 2:b_red 3:w3d 4:b3d 5:w2d 6:b2d 7:sample_mask (unused)
// ---------------------------------------------------------------------------
extern "C" void kernel_launch(void* const* d_in, const int* in_sizes, int n_in,
                              void* d_out, int out_size)
{
    const float* x     = (const float*)d_in[0];
    const float* w_red = (const float*)d_in[1];
    const float* b_red = (const float*)d_in[2];
    const float* w3d   = (const float*)d_in[3];
    const float* b3d   = (const float*)d_in[4];
    const float* w2d   = (const float*)d_in[5];
    const float* b2d   = (const float*)d_in[6];
    float* out = (float*)d_out;

    cudaFuncSetAttribute(interp_kernel,
                         cudaFuncAttributeMaxDynamicSharedMemorySize, INTERP_DSM);

    conv1d_kernel<<<BATCH*CHID, 128>>>(x, w_red, b_red);
    w3d_transpose_kernel<<<dim3(CROI, 4), 256>>>(w3d);
    pmat_kernel<<<dim3(4, NSMP, BATCH), 256>>>();
    interp_kernel<<<dim3(2, DSC, BO/128), 256, INTERP_DSM>>>(b3d);
    out_gemm_kernel<<<dim3(NDM/64, BATCH), 256>>>(w2d, b2d, out);
}